// round 8
// baseline (speedup 1.0000x reference)
#include <cuda_runtime.h>
#include <cuda_bf16.h>
#include <cstdint>
#include <math.h>

// MMD loss: B=4096, D=256, N=2B=8192.
// loss = (1/B^2) * sum_{i,j} sign(i,j) * K(i,j),  sign = +1 same block, -1 cross.
// K(i,j) = sum_{m=0..4} exp(-L2_ij / (bw*2^m)),  bw = (sum L2)/(N^2-N)/4.
// u = exp2(L2 * negc2) -> K = u+u^2+u^4+u^8+u^16.
// Gram matrix via mma.sync bf16. g_bf16 is stored CHUNK-CONTIGUOUS and
// PRE-SWIZZLED so each (tile, kchunk) stages with ONE cp.async.bulk per matrix.
// Layout: elem(row,c) -> (row>>7)*32768 + (c>>6)*8192 + (row&127)*64
//                        + (((c&63)>>3) ^ (row&7))*8 + (c&7)
// 8 warps/CTA (32x64 warp tiles) -> 16 warps/SM for latency hiding.

#define DDIM 256
#define CHUNK_B 16384           // 128 rows x 64 bf16 x 2B, contiguous
#define TILE_B  65536           // 4 chunks

__device__ __nv_bfloat16 g_bf16[8192 * 256]; // swizzled chunked [src; tgt]
__device__ float  g_sq[8192];
__device__ float  g_colsum[256];
__device__ float  g_negc2;                   // -log2(e)/(16*bw)
__device__ double g_accum;

// SMEM layout (dynamic): [A0 16K][A1 16K][B0 16K][B1 16K][mbar 2x8][sqa][sqb][red]
#define SM_A(buf)  ((uint32_t)(buf) << 14)
#define SM_B(buf)  (32768u + ((uint32_t)(buf) << 14))
#define SM_MBAR    65536u
#define SM_SQA     65552u
#define SM_SQB     66064u
#define SM_RED     66576u
#define SM_TOTAL   67600

// ---------------- helpers ---------------------------------------------------
__device__ __forceinline__ uint32_t smem_u32(const void* p) {
    uint32_t a;
    asm("{ .reg .u64 t; cvta.to.shared.u64 t, %1; cvt.u32.u64 %0, t; }" : "=r"(a) : "l"(p));
    return a;
}
__device__ __forceinline__ void ldsm4(uint32_t* r, uint32_t addr) {
    asm volatile("ldmatrix.sync.aligned.m8n8.x4.shared.b16 {%0,%1,%2,%3}, [%4];"
                 : "=r"(r[0]), "=r"(r[1]), "=r"(r[2]), "=r"(r[3]) : "r"(addr));
}
__device__ __forceinline__ void mma16816(float* c, const uint32_t* a, const uint32_t* b) {
    asm volatile(
        "mma.sync.aligned.m16n8k16.row.col.f32.bf16.bf16.f32 "
        "{%0,%1,%2,%3}, {%4,%5,%6,%7}, {%8,%9}, {%0,%1,%2,%3};"
        : "+f"(c[0]), "+f"(c[1]), "+f"(c[2]), "+f"(c[3])
        : "r"(a[0]), "r"(a[1]), "r"(a[2]), "r"(a[3]), "r"(b[0]), "r"(b[1]));
}
__device__ __forceinline__ void bulk_g2s(uint32_t dst, const void* src,
                                         uint32_t bytes, uint32_t mbar) {
    asm volatile(
        "cp.async.bulk.shared::cluster.global.mbarrier::complete_tx::bytes [%0], [%1], %2, [%3];"
        :: "r"(dst), "l"(src), "r"(bytes), "r"(mbar) : "memory");
}
#define MB_INIT(mb, c) asm volatile("mbarrier.init.shared.b64 [%0], %1;" :: "r"(mb), "r"(c) : "memory")
#define MB_EXPECT_TX(mb, n) asm volatile("mbarrier.arrive.expect_tx.shared.b64 _, [%0], %1;" :: "r"(mb), "r"(n) : "memory")
#define MB_WAIT(mb, par) do {                                                 \
    uint32_t _m = (mb), _p = (par), _d;                                       \
    asm volatile("{\n\t.reg .pred p;\n\t"                                     \
        "mbarrier.try_wait.parity.acquire.cta.shared::cta.b64 p, [%1], %2;\n\t" \
        "selp.b32 %0, 1, 0, p;\n\t}" : "=r"(_d) : "r"(_m), "r"(_p) : "memory"); \
    if (!_d) {                                                                \
        asm volatile("{\n\t.reg .pred P1;\n\t"                                \
            "W_%=:\n\t"                                                       \
            "mbarrier.try_wait.parity.acquire.cta.shared::cta.b64 P1, [%0], %1, 0x989680;\n\t" \
            "@P1 bra.uni D_%=;\n\t"                                           \
            "bra.uni W_%=;\n\t"                                               \
            "D_%=:\n\t}" :: "r"(_m), "r"(_p) : "memory");                     \
    }                                                                         \
} while (0)

__device__ __forceinline__ float fast_ex2(float x) {
    float r;
    asm("ex2.approx.ftz.f32 %0, %1;" : "=f"(r) : "f"(x));
    return r;
}

// ---------------------------------------------------------------------------
__global__ void k_zero() {
    g_colsum[threadIdx.x] = 0.f;
    if (threadIdx.x == 0) g_accum = 0.0;
}

// ---------------------------------------------------------------------------
// Round to bf16 and write into the swizzled chunk-contiguous layout.
// Row sq-norms and column sums FROM THE ROUNDED values.
__global__ void k_prep(const float* __restrict__ src,
                       const float* __restrict__ tgt, int B) {
    __shared__ float scol[256];
    scol[threadIdx.x] = 0.f;
    __syncthreads();

    const int warp = threadIdx.x >> 5;
    const int lane = threadIdx.x & 31;
    const int rowBase = blockIdx.x * 64 + warp * 8;

    float c0 = 0.f, c1 = 0.f, c2 = 0.f, c3 = 0.f;
    float c4 = 0.f, c5 = 0.f, c6 = 0.f, c7 = 0.f;

    const int ca = lane * 4;        // cols for v0
    const int cb = 128 + lane * 4;  // cols for v1

    #pragma unroll
    for (int r = 0; r < 8; ++r) {
        const int row = rowBase + r;
        const float* rp = (row < B) ? (src + (size_t)row * DDIM)
                                    : (tgt + (size_t)(row - B) * DDIM);
        float4 v0 = *(const float4*)(rp + ca);
        float4 v1 = *(const float4*)(rp + cb);

        __nv_bfloat162 h0 = __floats2bfloat162_rn(v0.x, v0.y);
        __nv_bfloat162 h1 = __floats2bfloat162_rn(v0.z, v0.w);
        __nv_bfloat162 h2 = __floats2bfloat162_rn(v1.x, v1.y);
        __nv_bfloat162 h3 = __floats2bfloat162_rn(v1.z, v1.w);

        uint2 p0 = make_uint2(*(uint32_t*)&h0, *(uint32_t*)&h1);
        uint2 p1 = make_uint2(*(uint32_t*)&h2, *(uint32_t*)&h3);

        // swizzled chunk-contiguous addresses (element units)
        const int tOff = (row >> 7) * 32768;
        const int rl   = row & 127;
        const int rx   = rl & 7;
        size_t e0 = (size_t)tOff + (ca >> 6) * 8192 + rl * 64
                  + ((((ca & 63) >> 3) ^ rx) * 8) + (ca & 7);
        size_t e1 = (size_t)tOff + (cb >> 6) * 8192 + rl * 64
                  + ((((cb & 63) >> 3) ^ rx) * 8) + (cb & 7);
        *(uint2*)(g_bf16 + e0) = p0;
        *(uint2*)(g_bf16 + e1) = p1;

        float x0 = __low2float(h0), x1 = __high2float(h0);
        float x2 = __low2float(h1), x3 = __high2float(h1);
        float x4 = __low2float(h2), x5 = __high2float(h2);
        float x6 = __low2float(h3), x7 = __high2float(h3);

        float ss = x0*x0 + x1*x1 + x2*x2 + x3*x3 + x4*x4 + x5*x5 + x6*x6 + x7*x7;
        #pragma unroll
        for (int o = 16; o; o >>= 1) ss += __shfl_xor_sync(0xffffffffu, ss, o);
        if (lane == 0) g_sq[row] = ss;

        c0 += x0; c1 += x1; c2 += x2; c3 += x3;
        c4 += x4; c5 += x5; c6 += x6; c7 += x7;
    }

    atomicAdd(&scol[lane * 4 + 0], c0);
    atomicAdd(&scol[lane * 4 + 1], c1);
    atomicAdd(&scol[lane * 4 + 2], c2);
    atomicAdd(&scol[lane * 4 + 3], c3);
    atomicAdd(&scol[128 + lane * 4 + 0], c4);
    atomicAdd(&scol[128 + lane * 4 + 1], c5);
    atomicAdd(&scol[128 + lane * 4 + 2], c6);
    atomicAdd(&scol[128 + lane * 4 + 3], c7);
    __syncthreads();
    atomicAdd(&g_colsum[threadIdx.x], scol[threadIdx.x]);
}

// ---------------------------------------------------------------------------
__global__ void k_bw(int B) {
    const int N = 2 * B;
    __shared__ double sh[256];
    const int t = threadIdx.x;

    double s = 0.0;
    for (int i = t; i < N; i += 256) s += (double)g_sq[i];
    sh[t] = s;
    __syncthreads();
    for (int st = 128; st; st >>= 1) {
        if (t < st) sh[t] += sh[t + st];
        __syncthreads();
    }
    double sumsq = sh[0];
    __syncthreads();

    float c = g_colsum[t];
    sh[t] = (double)c * (double)c;
    __syncthreads();
    for (int st = 128; st; st >>= 1) {
        if (t < st) sh[t] += sh[t + st];
        __syncthreads();
    }
    if (t == 0) {
        double ssq   = sh[0];
        double sumL2 = 2.0 * (double)N * sumsq - 2.0 * ssq;
        double bw    = sumL2 / ((double)N * (double)N - (double)N);
        bw /= 4.0;  // KERNEL_MUL^(KERNEL_NUM//2) = 2^2
        g_negc2 = (float)(-1.4426950408889634 / (16.0 * bw));
        g_accum = 0.0;
    }
}

// ---------------------------------------------------------------------------
// 128x128 Gram tile per CTA; 8 warps (4x2), 32x64 each. K in 4 chunks of 64,
// double-buffered via cp.async.bulk + mbarrier. Fused Gaussian epilogue.
__global__ void __launch_bounds__(256, 2) k_mmd(int B, int NT) {
    extern __shared__ __align__(16) char smem[];
    const uint32_t sbase = smem_u32(smem);
    const int t = threadIdx.x;
    const int wid = t >> 5, lane = t & 31;

    // decode linear upper-triangular index -> (ti, tj), tj >= ti.
    const int idx = blockIdx.x;
    float fn = (float)NT + 0.5f;
    int ti = (int)(fn - sqrtf(fn * fn - 2.0f * (float)idx));
    while (ti * NT - (ti * (ti - 1)) / 2 > idx) --ti;
    while ((ti + 1) * NT - ((ti + 1) * ti) / 2 <= idx) ++ti;
    const int tj = ti + (idx - (ti * NT - (ti * (ti - 1)) / 2));

    if (t == 0) {
        MB_INIT(sbase + SM_MBAR, 1);
        MB_INIT(sbase + SM_MBAR + 8, 1);
    }
    if (t < 128) {
        *(float*)(smem + SM_SQA + t * 4) = g_sq[ti * 128 + t];
        *(float*)(smem + SM_SQB + t * 4) = g_sq[tj * 128 + t];
    }
    __syncthreads();

    const char* gA = (const char*)g_bf16 + (size_t)ti * TILE_B;
    const char* gB = (const char*)g_bf16 + (size_t)tj * TILE_B;

    // stage chunk kc into buffer buf (2 bulk copies, one mbarrier)
    auto stage = [&](int kc, int buf) {
        const uint32_t mb = sbase + SM_MBAR + (uint32_t)buf * 8;
        MB_EXPECT_TX(mb, 2 * CHUNK_B);
        bulk_g2s(sbase + SM_A(buf), gA + (size_t)kc * CHUNK_B, CHUNK_B, mb);
        bulk_g2s(sbase + SM_B(buf), gB + (size_t)kc * CHUNK_B, CHUNK_B, mb);
    };
    if (t == 0) { stage(0, 0); stage(1, 1); }

    // warp tile: rows (wid&3)*32, cols (wid>>2)*64
    const int wrow = (wid & 3) * 32;
    const int wcol = (wid >> 2) * 64;
    const uint32_t xr  = (uint32_t)(lane & 7);
    const uint32_t hiA = (uint32_t)(lane >> 4);          // 0..1
    const uint32_t hiB = (uint32_t)((lane >> 3) & 1);    // 0..1
    uint32_t aRowOff[2], bRowOff[4];
    #pragma unroll
    for (int m = 0; m < 2; ++m)
        aRowOff[m] = (uint32_t)(wrow + m * 16 + (lane & 15)) * 128;
    #pragma unroll
    for (int p = 0; p < 4; ++p)
        bRowOff[p] = (uint32_t)(wcol + (lane & 7) + ((lane >> 4) & 1) * 8 + p * 16) * 128;

    float acc[2][8][4];
    #pragma unroll
    for (int m = 0; m < 2; ++m)
        #pragma unroll
        for (int n = 0; n < 8; ++n)
            #pragma unroll
            for (int r = 0; r < 4; ++r) acc[m][n][r] = 0.f;

    #pragma unroll 1
    for (int c = 0; c < 4; ++c) {
        const int buf = c & 1;
        MB_WAIT(sbase + SM_MBAR + (uint32_t)buf * 8, (c >> 1) & 1);

        const uint32_t aB = sbase + SM_A(buf);
        const uint32_t bB = sbase + SM_B(buf);
        #pragma unroll
        for (int ks = 0; ks < 4; ++ks) {
            uint32_t af[2][4], bf_[4][4];
            const uint32_t sgA = ((uint32_t)(ks * 2) + hiA) ^ xr;
            const uint32_t sgB = ((uint32_t)(ks * 2) + hiB) ^ xr;
            #pragma unroll
            for (int m = 0; m < 2; ++m)
                ldsm4(af[m], aB + aRowOff[m] + (sgA << 4));
            #pragma unroll
            for (int p = 0; p < 4; ++p)
                ldsm4(bf_[p], bB + bRowOff[p] + (sgB << 4));

            #pragma unroll
            for (int m = 0; m < 2; ++m)
                #pragma unroll
                for (int p = 0; p < 4; ++p) {
                    mma16816(acc[m][2 * p],     af[m], &bf_[p][0]);
                    mma16816(acc[m][2 * p + 1], af[m], &bf_[p][2]);
                }
        }
        __syncthreads();                  // all warps done reading buf
        if (c + 2 < 4 && t == 0) stage(c + 2, buf);
    }

    // -------- fused epilogue: L2 -> sum of 5 Gaussian kernels --------
    const float negc2 = g_negc2;
    const float* sqa = (const float*)(smem + SM_SQA);
    const float* sqb = (const float*)(smem + SM_SQB);
    // C[row][col]: row = wrow + m*16 + (lane>>2) + 8*(r>>1)
    //              col = wcol + n*8 + (lane&3)*2 + (r&1)
    float sa[4], sb[16];
    #pragma unroll
    for (int m = 0; m < 2; ++m)
        #pragma unroll
        for (int h = 0; h < 2; ++h)
            sa[m * 2 + h] = sqa[wrow + m * 16 + (lane >> 2) + h * 8];
    #pragma unroll
    for (int n = 0; n < 8; ++n) {
        sb[n * 2 + 0] = sqb[wcol + n * 8 + (lane & 3) * 2 + 0];
        sb[n * 2 + 1] = sqb[wcol + n * 8 + (lane & 3) * 2 + 1];
    }

    float tsum = 0.f;
    #pragma unroll
    for (int m = 0; m < 2; ++m)
        #pragma unroll
        for (int n = 0; n < 8; ++n)
            #pragma unroll
            for (int r = 0; r < 4; ++r) {
                float d  = acc[m][n][r];
                float l2 = fmaf(-2.f, d, sa[m * 2 + (r >> 1)] + sb[n * 2 + (r & 1)]);
                float u  = fast_ex2(l2 * negc2);
                float u2 = u * u, u4 = u2 * u2, u8 = u4 * u4, u16 = u8 * u8;
                tsum += (u + u2) + (u4 + u8) + u16;
            }

    float* red = (float*)(smem + SM_RED);
    red[t] = tsum;
    __syncthreads();
    #pragma unroll
    for (int st = 128; st; st >>= 1) {
        if (t < st) red[t] += red[t + st];
        __syncthreads();
    }
    if (t == 0) {
        bool  si   = (ti * 128) < B;
        bool  sj   = (tj * 128) < B;
        float w    = (ti == tj) ? 1.f : 2.f;
        float sgnw = (si == sj) ? w : -w;
        atomicAdd(&g_accum, (double)(red[0] * sgnw));
    }
}

// ---------------------------------------------------------------------------
__global__ void k_final(float* out, int B) {
    out[0] = (float)(g_accum / ((double)B * (double)B));
}

// ---------------------------------------------------------------------------
extern "C" void kernel_launch(void* const* d_in, const int* in_sizes, int n_in,
                              void* d_out, int out_size) {
    const float* src = (const float*)d_in[0];
    const float* tgt = (const float*)d_in[1];
    const int B = in_sizes[0] / DDIM;   // 4096
    const int N = 2 * B;                // 8192
    const int NT = N / 128;             // 64 tiles per dim

    cudaFuncSetAttribute(k_mmd, cudaFuncAttributeMaxDynamicSharedMemorySize, SM_TOTAL);

    k_zero<<<1, 256>>>();
    k_prep<<<N / 64, 256>>>(src, tgt, B);
    k_bw<<<1, 256>>>(B);
    const int ntri = NT * (NT + 1) / 2; // 2080 upper-triangular tiles
    k_mmd<<<ntri, 256, SM_TOTAL>>>(B, NT);
    k_final<<<1, 1>>>((float*)d_out, B);
}

// round 9
// speedup vs baseline: 1.0173x; 1.0173x over previous
#include <cuda_runtime.h>
#include <cuda_bf16.h>
#include <cstdint>
#include <math.h>

// MMD loss: B=4096, D=256, N=2B=8192.
// loss = (1/B^2) * sum_{i,j} sign(i,j) * K(i,j),  sign = +1 same block, -1 cross.
// K(i,j) = sum_{m=0..4} exp(-L2_ij / (bw*2^m)),  bw = (sum L2)/(N^2-N)/4.
// u = exp2(L2 * negc2) -> K = u+u^2+u^4+u^8+u^16.
// Gram matrix via mma.sync bf16 from pre-swizzled chunk-contiguous g_bf16
// (one cp.async.bulk per matrix per chunk). PERSISTENT CTAs (2/SM) with
// cross-tile TMA prefetch; packed-f32x2 fused Gaussian epilogue.

#define DDIM 256
#define CHUNK_B 16384           // 128 rows x 64 bf16 x 2B, contiguous
#define TILE_B  65536           // 4 chunks
#define NCTA    296             // 2 per SM on 148-SM B200

__device__ __nv_bfloat16 g_bf16[8192 * 256]; // swizzled chunked [src; tgt]
__device__ float  g_sq[8192];
__device__ float  g_colsum[256];
__device__ float  g_negc2;                   // -log2(e)/(16*bw)
__device__ double g_accum;

// SMEM layout (dynamic): [A0 16K][A1 16K][B0 16K][B1 16K][mbar 2x8][red 8]
#define SM_A(buf)  ((uint32_t)(buf) << 14)
#define SM_B(buf)  (32768u + ((uint32_t)(buf) << 14))
#define SM_MBAR    65536u
#define SM_RED     65568u
#define SM_TOTAL   65664

// ---------------- helpers ---------------------------------------------------
__device__ __forceinline__ uint32_t smem_u32(const void* p) {
    uint32_t a;
    asm("{ .reg .u64 t; cvta.to.shared.u64 t, %1; cvt.u32.u64 %0, t; }" : "=r"(a) : "l"(p));
    return a;
}
__device__ __forceinline__ void ldsm4(uint32_t* r, uint32_t addr) {
    asm volatile("ldmatrix.sync.aligned.m8n8.x4.shared.b16 {%0,%1,%2,%3}, [%4];"
                 : "=r"(r[0]), "=r"(r[1]), "=r"(r[2]), "=r"(r[3]) : "r"(addr));
}
__device__ __forceinline__ void mma16816(float* c, const uint32_t* a, const uint32_t* b) {
    asm volatile(
        "mma.sync.aligned.m16n8k16.row.col.f32.bf16.bf16.f32 "
        "{%0,%1,%2,%3}, {%4,%5,%6,%7}, {%8,%9}, {%0,%1,%2,%3};"
        : "+f"(c[0]), "+f"(c[1]), "+f"(c[2]), "+f"(c[3])
        : "r"(a[0]), "r"(a[1]), "r"(a[2]), "r"(a[3]), "r"(b[0]), "r"(b[1]));
}
__device__ __forceinline__ void bulk_g2s(uint32_t dst, const void* src,
                                         uint32_t bytes, uint32_t mbar) {
    asm volatile(
        "cp.async.bulk.shared::cluster.global.mbarrier::complete_tx::bytes [%0], [%1], %2, [%3];"
        :: "r"(dst), "l"(src), "r"(bytes), "r"(mbar) : "memory");
}
#define MB_INIT(mb, c) asm volatile("mbarrier.init.shared.b64 [%0], %1;" :: "r"(mb), "r"(c) : "memory")
#define MB_EXPECT_TX(mb, n) asm volatile("mbarrier.arrive.expect_tx.shared.b64 _, [%0], %1;" :: "r"(mb), "r"(n) : "memory")
#define MB_WAIT(mb, par) do {                                                 \
    uint32_t _m = (mb), _p = (par), _d;                                       \
    asm volatile("{\n\t.reg .pred p;\n\t"                                     \
        "mbarrier.try_wait.parity.acquire.cta.shared::cta.b64 p, [%1], %2;\n\t" \
        "selp.b32 %0, 1, 0, p;\n\t}" : "=r"(_d) : "r"(_m), "r"(_p) : "memory"); \
    if (!_d) {                                                                \
        asm volatile("{\n\t.reg .pred P1;\n\t"                                \
            "W_%=:\n\t"                                                       \
            "mbarrier.try_wait.parity.acquire.cta.shared::cta.b64 P1, [%0], %1, 0x989680;\n\t" \
            "@P1 bra.uni D_%=;\n\t"                                           \
            "bra.uni W_%=;\n\t"                                               \
            "D_%=:\n\t}" :: "r"(_m), "r"(_p) : "memory");                     \
    }                                                                         \
} while (0)

__device__ __forceinline__ float fast_ex2(float x) {
    float r;
    asm("ex2.approx.ftz.f32 %0, %1;" : "=f"(r) : "f"(x));
    return r;
}

// packed f32x2 via fma.rn.f32x2 only (proven on this toolchain)
typedef unsigned long long u64t;
__device__ __forceinline__ u64t f2pack(float lo, float hi) {
    u64t r; asm("mov.b64 %0, {%1, %2};" : "=l"(r) : "f"(lo), "f"(hi)); return r;
}
__device__ __forceinline__ void f2unpack(u64t v, float& lo, float& hi) {
    asm("mov.b64 {%0, %1}, %2;" : "=f"(lo), "=f"(hi) : "l"(v));
}
__device__ __forceinline__ u64t f2fma(u64t a, u64t b, u64t c) {
    u64t d; asm("fma.rn.f32x2 %0, %1, %2, %3;" : "=l"(d) : "l"(a), "l"(b), "l"(c)); return d;
}

__device__ __forceinline__ void tri_decode(int idx, int NT, int& ti, int& tj) {
    float fn = (float)NT + 0.5f;
    int a = (int)(fn - sqrtf(fn * fn - 2.0f * (float)idx));
    while (a * NT - (a * (a - 1)) / 2 > idx) --a;
    while ((a + 1) * NT - ((a + 1) * a) / 2 <= idx) ++a;
    ti = a;
    tj = a + (idx - (a * NT - (a * (a - 1)) / 2));
}

// ---------------------------------------------------------------------------
__global__ void k_zero() {
    g_colsum[threadIdx.x] = 0.f;
    if (threadIdx.x == 0) g_accum = 0.0;
}

// ---------------------------------------------------------------------------
// Round to bf16 and write into the swizzled chunk-contiguous layout.
// Row sq-norms and column sums FROM THE ROUNDED values.
__global__ void k_prep(const float* __restrict__ src,
                       const float* __restrict__ tgt, int B) {
    __shared__ float scol[256];
    scol[threadIdx.x] = 0.f;
    __syncthreads();

    const int warp = threadIdx.x >> 5;
    const int lane = threadIdx.x & 31;
    const int rowBase = blockIdx.x * 64 + warp * 8;

    float c0 = 0.f, c1 = 0.f, c2 = 0.f, c3 = 0.f;
    float c4 = 0.f, c5 = 0.f, c6 = 0.f, c7 = 0.f;

    const int ca = lane * 4;
    const int cb = 128 + lane * 4;

    #pragma unroll
    for (int r = 0; r < 8; ++r) {
        const int row = rowBase + r;
        const float* rp = (row < B) ? (src + (size_t)row * DDIM)
                                    : (tgt + (size_t)(row - B) * DDIM);
        float4 v0 = *(const float4*)(rp + ca);
        float4 v1 = *(const float4*)(rp + cb);

        __nv_bfloat162 h0 = __floats2bfloat162_rn(v0.x, v0.y);
        __nv_bfloat162 h1 = __floats2bfloat162_rn(v0.z, v0.w);
        __nv_bfloat162 h2 = __floats2bfloat162_rn(v1.x, v1.y);
        __nv_bfloat162 h3 = __floats2bfloat162_rn(v1.z, v1.w);

        uint2 p0 = make_uint2(*(uint32_t*)&h0, *(uint32_t*)&h1);
        uint2 p1 = make_uint2(*(uint32_t*)&h2, *(uint32_t*)&h3);

        const int tOff = (row >> 7) * 32768;
        const int rl   = row & 127;
        const int rx   = rl & 7;
        size_t e0 = (size_t)tOff + (ca >> 6) * 8192 + rl * 64
                  + ((((ca & 63) >> 3) ^ rx) * 8) + (ca & 7);
        size_t e1 = (size_t)tOff + (cb >> 6) * 8192 + rl * 64
                  + ((((cb & 63) >> 3) ^ rx) * 8) + (cb & 7);
        *(uint2*)(g_bf16 + e0) = p0;
        *(uint2*)(g_bf16 + e1) = p1;

        float x0 = __low2float(h0), x1 = __high2float(h0);
        float x2 = __low2float(h1), x3 = __high2float(h1);
        float x4 = __low2float(h2), x5 = __high2float(h2);
        float x6 = __low2float(h3), x7 = __high2float(h3);

        float ss = x0*x0 + x1*x1 + x2*x2 + x3*x3 + x4*x4 + x5*x5 + x6*x6 + x7*x7;
        #pragma unroll
        for (int o = 16; o; o >>= 1) ss += __shfl_xor_sync(0xffffffffu, ss, o);
        if (lane == 0) g_sq[row] = ss;

        c0 += x0; c1 += x1; c2 += x2; c3 += x3;
        c4 += x4; c5 += x5; c6 += x6; c7 += x7;
    }

    atomicAdd(&scol[lane * 4 + 0], c0);
    atomicAdd(&scol[lane * 4 + 1], c1);
    atomicAdd(&scol[lane * 4 + 2], c2);
    atomicAdd(&scol[lane * 4 + 3], c3);
    atomicAdd(&scol[128 + lane * 4 + 0], c4);
    atomicAdd(&scol[128 + lane * 4 + 1], c5);
    atomicAdd(&scol[128 + lane * 4 + 2], c6);
    atomicAdd(&scol[128 + lane * 4 + 3], c7);
    __syncthreads();
    atomicAdd(&g_colsum[threadIdx.x], scol[threadIdx.x]);
}

// ---------------------------------------------------------------------------
__global__ void k_bw(int B) {
    const int N = 2 * B;
    __shared__ double sh[256];
    const int t = threadIdx.x;

    double s = 0.0;
    for (int i = t; i < N; i += 256) s += (double)g_sq[i];
    sh[t] = s;
    __syncthreads();
    for (int st = 128; st; st >>= 1) {
        if (t < st) sh[t] += sh[t + st];
        __syncthreads();
    }
    double sumsq = sh[0];
    __syncthreads();

    float c = g_colsum[t];
    sh[t] = (double)c * (double)c;
    __syncthreads();
    for (int st = 128; st; st >>= 1) {
        if (t < st) sh[t] += sh[t + st];
        __syncthreads();
    }
    if (t == 0) {
        double ssq   = sh[0];
        double sumL2 = 2.0 * (double)N * sumsq - 2.0 * ssq;
        double bw    = sumL2 / ((double)N * (double)N - (double)N);
        bw /= 4.0;  // KERNEL_MUL^(KERNEL_NUM//2) = 2^2
        g_negc2 = (float)(-1.4426950408889634 / (16.0 * bw));
        g_accum = 0.0;
    }
}

// ---------------------------------------------------------------------------
// Persistent: each CTA loops over upper-triangular 128x128 tiles.
// 8 warps (4x2), 32x64 per warp. K in 4 chunks of 64, double-buffered via
// cp.async.bulk; NEXT tile's chunks prefetched under the epilogue.
__global__ void __launch_bounds__(256, 2) k_mmd(int B, int NT, int ntri) {
    extern __shared__ __align__(16) char smem[];
    const uint32_t sbase = smem_u32(smem);
    const int t = threadIdx.x;
    const int wid = t >> 5, lane = t & 31;

    if (t == 0) {
        MB_INIT(sbase + SM_MBAR, 1);
        MB_INIT(sbase + SM_MBAR + 8, 1);
    }
    __syncthreads();

    // warp tile: rows (wid&3)*32, cols (wid>>2)*64
    const int wrow = (wid & 3) * 32;
    const int wcol = (wid >> 2) * 64;
    const uint32_t xr  = (uint32_t)(lane & 7);
    const uint32_t hiA = (uint32_t)(lane >> 4);
    const uint32_t hiB = (uint32_t)((lane >> 3) & 1);
    uint32_t aRowOff[2], bRowOff[4];
    #pragma unroll
    for (int m = 0; m < 2; ++m)
        aRowOff[m] = (uint32_t)(wrow + m * 16 + (lane & 15)) * 128;
    #pragma unroll
    for (int p = 0; p < 4; ++p)
        bRowOff[p] = (uint32_t)(wcol + (lane & 7) + ((lane >> 4) & 1) * 8 + p * 16) * 128;

    int idx = blockIdx.x;
    if (idx >= ntri) return;
    int ti, tj;
    tri_decode(idx, NT, ti, tj);

    int ph0 = 0, ph1 = 0;     // per-buffer wait counters (parity = count&1)

    // initial stage: chunks 0,1 of first tile
    if (t == 0) {
        const char* gA = (const char*)g_bf16 + (size_t)ti * TILE_B;
        const char* gB = (const char*)g_bf16 + (size_t)tj * TILE_B;
        MB_EXPECT_TX(sbase + SM_MBAR, 2 * CHUNK_B);
        bulk_g2s(sbase + SM_A(0), gA, CHUNK_B, sbase + SM_MBAR);
        bulk_g2s(sbase + SM_B(0), gB, CHUNK_B, sbase + SM_MBAR);
        MB_EXPECT_TX(sbase + SM_MBAR + 8, 2 * CHUNK_B);
        bulk_g2s(sbase + SM_A(1), gA + CHUNK_B, CHUNK_B, sbase + SM_MBAR + 8);
        bulk_g2s(sbase + SM_B(1), gB + CHUNK_B, CHUNK_B, sbase + SM_MBAR + 8);
    }

    const float negc2 = g_negc2;
    const u64t ZERO = 0ull;
    const u64t ONE  = f2pack(1.f, 1.f);
    const u64t M2   = f2pack(-2.f, -2.f);
    const u64t NCD  = f2pack(negc2, negc2);

    while (true) {
        const int nidx = idx + gridDim.x;
        const bool has_next = (nidx < ntri);
        int ti2 = 0, tj2 = 0;
        if (has_next) tri_decode(nidx, NT, ti2, tj2);
        const char* gA2 = (const char*)g_bf16 + (size_t)ti2 * TILE_B;
        const char* gB2 = (const char*)g_bf16 + (size_t)tj2 * TILE_B;

        float acc[2][8][4];
        #pragma unroll
        for (int m = 0; m < 2; ++m)
            #pragma unroll
            for (int n = 0; n < 8; ++n)
                #pragma unroll
                for (int r = 0; r < 4; ++r) acc[m][n][r] = 0.f;

        #pragma unroll 1
        for (int c = 0; c < 4; ++c) {
            const int buf = c & 1;
            if (buf == 0) { MB_WAIT(sbase + SM_MBAR,     ph0 & 1); ++ph0; }
            else          { MB_WAIT(sbase + SM_MBAR + 8, ph1 & 1); ++ph1; }

            const uint32_t aB = sbase + SM_A(buf);
            const uint32_t bB = sbase + SM_B(buf);
            #pragma unroll
            for (int ks = 0; ks < 4; ++ks) {
                uint32_t af[2][4], bf_[4][4];
                const uint32_t sgA = ((uint32_t)(ks * 2) + hiA) ^ xr;
                const uint32_t sgB = ((uint32_t)(ks * 2) + hiB) ^ xr;
                #pragma unroll
                for (int m = 0; m < 2; ++m)
                    ldsm4(af[m], aB + aRowOff[m] + (sgA << 4));
                #pragma unroll
                for (int p = 0; p < 4; ++p)
                    ldsm4(bf_[p], bB + bRowOff[p] + (sgB << 4));

                #pragma unroll
                for (int m = 0; m < 2; ++m)
                    #pragma unroll
                    for (int p = 0; p < 4; ++p) {
                        mma16816(acc[m][2 * p],     af[m], &bf_[p][0]);
                        mma16816(acc[m][2 * p + 1], af[m], &bf_[p][2]);
                    }
            }
            __syncthreads();                  // all warps done reading buf
            // prefetch: current tile chunk c+2, or NEXT tile's chunk c-2
            if (t == 0) {
                if (c < 2) {
                    const char* gA1 = (const char*)g_bf16 + (size_t)ti * TILE_B;
                    const char* gB1 = (const char*)g_bf16 + (size_t)tj * TILE_B;
                    const uint32_t mb = sbase + SM_MBAR + (uint32_t)buf * 8;
                    MB_EXPECT_TX(mb, 2 * CHUNK_B);
                    bulk_g2s(sbase + SM_A(buf), gA1 + (size_t)(c + 2) * CHUNK_B, CHUNK_B, mb);
                    bulk_g2s(sbase + SM_B(buf), gB1 + (size_t)(c + 2) * CHUNK_B, CHUNK_B, mb);
                } else if (has_next) {
                    const uint32_t mb = sbase + SM_MBAR + (uint32_t)buf * 8;
                    MB_EXPECT_TX(mb, 2 * CHUNK_B);
                    bulk_g2s(sbase + SM_A(buf), gA2 + (size_t)(c - 2) * CHUNK_B, CHUNK_B, mb);
                    bulk_g2s(sbase + SM_B(buf), gB2 + (size_t)(c - 2) * CHUNK_B, CHUNK_B, mb);
                }
            }
        }

        // -------- fused epilogue (packed f32x2): L2 -> 5-kernel sum --------
        const float* sqaRow = g_sq + ti * 128 + wrow + (lane >> 2);
        const float* sqbRow = g_sq + tj * 128 + wcol + (lane & 3) * 2;
        u64t sadup[4];
        #pragma unroll
        for (int m = 0; m < 2; ++m)
            #pragma unroll
            for (int h = 0; h < 2; ++h) {
                float v = sqaRow[m * 16 + h * 8];
                sadup[m * 2 + h] = f2pack(v, v);
            }
        u64t sbp[8];
        #pragma unroll
        for (int n = 0; n < 8; ++n)
            sbp[n] = *(const u64t*)(sqbRow + n * 8);

        u64t tsp = ZERO;
        #pragma unroll
        for (int m = 0; m < 2; ++m)
            #pragma unroll
            for (int n = 0; n < 8; ++n)
                #pragma unroll
                for (int h = 0; h < 2; ++h) {
                    u64t dp   = f2pack(acc[m][n][2 * h], acc[m][n][2 * h + 1]);
                    u64t addp = f2fma(sadup[m * 2 + h], ONE, sbp[n]);
                    u64t l2p  = f2fma(dp, M2, addp);
                    u64t xp   = f2fma(l2p, NCD, ZERO);
                    float x0, x1;
                    f2unpack(xp, x0, x1);
                    u64t up  = f2pack(fast_ex2(x0), fast_ex2(x1));
                    u64t u2  = f2fma(up, up, ZERO);
                    u64t u4  = f2fma(u2, u2, ZERO);
                    u64t u8  = f2fma(u4, u4, ZERO);
                    u64t u16 = f2fma(u8, u8, ZERO);
                    u64t s1  = f2fma(up, ONE, u2);
                    u64t s2  = f2fma(u4, ONE, u8);
                    u64t s3  = f2fma(s1, ONE, u16);
                    u64t s4  = f2fma(s2, ONE, s3);
                    tsp = f2fma(s4, ONE, tsp);
                }
        float tlo, thi;
        f2unpack(tsp, tlo, thi);
        float tsum = tlo + thi;

        // warp reduce + cross-warp via smem + single atomic
        #pragma unroll
        for (int o = 16; o; o >>= 1) tsum += __shfl_xor_sync(0xffffffffu, tsum, o);
        float* red = (float*)(smem + SM_RED);
        if (lane == 0) red[wid] = tsum;
        __syncthreads();
        if (wid == 0) {
            float v = (lane < 8) ? red[lane] : 0.f;
            #pragma unroll
            for (int o = 4; o; o >>= 1) v += __shfl_xor_sync(0xffffffffu, v, o);
            if (lane == 0) {
                bool  si   = (ti * 128) < B;
                bool  sj   = (tj * 128) < B;
                float w    = (ti == tj) ? 1.f : 2.f;
                float sgnw = (si == sj) ? w : -w;
                atomicAdd(&g_accum, (double)(v * sgnw));
            }
        }

        if (!has_next) break;
        idx = nidx; ti = ti2; tj = tj2;
    }
}

// ---------------------------------------------------------------------------
__global__ void k_final(float* out, int B) {
    out[0] = (float)(g_accum / ((double)B * (double)B));
}

// ---------------------------------------------------------------------------
extern "C" void kernel_launch(void* const* d_in, const int* in_sizes, int n_in,
                              void* d_out, int out_size) {
    const float* src = (const float*)d_in[0];
    const float* tgt = (const float*)d_in[1];
    const int B = in_sizes[0] / DDIM;   // 4096
    const int N = 2 * B;                // 8192
    const int NT = N / 128;             // 64 tiles per dim

    cudaFuncSetAttribute(k_mmd, cudaFuncAttributeMaxDynamicSharedMemorySize, SM_TOTAL);

    k_zero<<<1, 256>>>();
    k_prep<<<N / 64, 256>>>(src, tgt, B);
    k_bw<<<1, 256>>>(B);
    const int ntri = NT * (NT + 1) / 2; // 2080 upper-triangular tiles
    const int ncta = (ntri < NCTA) ? ntri : NCTA;
    k_mmd<<<ncta, 256, SM_TOTAL>>>(B, NT, ntri);
    k_final<<<1, 1>>>((float*)d_out, B);
}